// round 3
// baseline (speedup 1.0000x reference)
#include <cuda_runtime.h>

#define BB 16
#define CC 256
#define HH 64
#define WW 64
#define SS 512
#define HW (HH*WW)

// Scratch (static __device__ arrays: allocation-free per harness rules)
__device__ float g_inter[BB*CC*HW];          // intermediate activation
__device__ float g_style[BB*CC];
__device__ float g_demod[BB*CC];
__device__ float g_Rt[CC*CC];                // Rt[ci*CC + o] = sum_k W[o,ci,k]^2
__device__ float g_Wt[CC*9*CC];              // Wt[ci*9*CC + k*CC + o] = W[o,ci,k]

typedef unsigned long long u64;

__device__ __forceinline__ u64 ffma2(u64 a, u64 b, u64 c) {
    u64 d;
    asm("fma.rn.f32x2 %0, %1, %2, %3;" : "=l"(d) : "l"(a), "l"(b), "l"(c));
    return d;
}
__device__ __forceinline__ float f2lo(u64 v) { return __uint_as_float((unsigned)v); }
__device__ __forceinline__ float f2hi(u64 v) { return __uint_as_float((unsigned)(v >> 32)); }

// ---------------------------------------------------------------------------
// style[b,i] = (sum_s wv[b,s] * sw[i,s]) * (1/32) + sb[i]
// ---------------------------------------------------------------------------
__global__ void k_style(const float* __restrict__ wv,
                        const float* __restrict__ sw,
                        const float* __restrict__ sb) {
    __shared__ float s[SS];
    const int b = blockIdx.x, t = threadIdx.x;
    s[t]       = wv[b*SS + t];
    s[t + 256] = wv[b*SS + 256 + t];
    __syncthreads();
    float acc = 0.f;
    const float* rw = sw + t*SS;
    #pragma unroll 8
    for (int j = 0; j < SS; j++) acc += s[j] * rw[j];
    g_style[b*CC + t] = acc * 0.03125f + sb[t];
}

// ---------------------------------------------------------------------------
// Transpose W[o,ci,k] -> Wt[ci,k,o] and Rt[ci,o] = sum_k W^2
// ---------------------------------------------------------------------------
__global__ void k_prep(const float* __restrict__ w) {
    const int ci = blockIdx.x, o = threadIdx.x;
    const float* src = w + (o*CC + ci)*9;
    float s2 = 0.f;
    #pragma unroll
    for (int k = 0; k < 9; k++) {
        float v = src[k];
        s2 += v * v;
        g_Wt[ci*(9*CC) + k*CC + o] = v;
    }
    g_Rt[ci*CC + o] = s2;
}

// ---------------------------------------------------------------------------
// demod[b,o] = rsqrt(sum_i style[b,i]^2 * Rt[i,o] + 1e-8)
// ---------------------------------------------------------------------------
__global__ void k_demod() {
    __shared__ float st2[CC];
    const int b = blockIdx.x, t = threadIdx.x;
    float s = g_style[b*CC + t];
    st2[t] = s * s;
    __syncthreads();
    float acc = 0.f;
    #pragma unroll 8
    for (int i = 0; i < CC; i++) acc += st2[i] * g_Rt[i*CC + t];
    g_demod[b*CC + t] = rsqrtf(acc + 1e-8f);
}

// ---------------------------------------------------------------------------
// Modulated 3x3 conv (batch-shared weights, style folded into weights) +
// demod + noise + leaky ReLU.  Software-pipelined over ci with double-buffered
// smem and register staging of the next tile.
// Block: 8 rows x 64 cols x 32 ocs, 256 threads.
// Thread: 8 cols x 8 ocs (4 f32x2 oc-pairs).
// ---------------------------------------------------------------------------
__global__ __launch_bounds__(256, 2)
void k_conv(const float* __restrict__ in, float* __restrict__ out,
            const float* __restrict__ noise, const float* __restrict__ nw) {
    __shared__ __align__(16) float2 s_in[2][660];   // splatted raw x tile
    __shared__ __align__(16) float  s_w[2][292];    // style-scaled weights [k][oc]
    __shared__ float s_style[CC];

    const float* inp  = in  ? in  : g_inter;
    float*       outp = out ? out : g_inter;

    const int tid  = threadIdx.x;
    const int y0   = blockIdx.x * 8;
    const int oc0  = blockIdx.y * 32;
    const int b    = blockIdx.z;
    const int g    = tid >> 6;          // 0..3 (oc group)
    const int slot = tid & 63;
    const int r    = slot & 7;          // output row in tile
    const int cg   = slot >> 3;         // col group
    const int x0   = cg * 8;            // first output col

    s_style[tid] = g_style[b*CC + tid];

    // ---- hoisted per-thread load descriptors (negative offset == zero-fill)
    int goff0, goff1, goff2;
    {
        int idx = tid;
        int row = idx / 66, col = idx - row*66;
        int gy = y0 - 1 + row, gx = col - 1;
        goff0 = ((unsigned)gy < (unsigned)HH && (unsigned)gx < (unsigned)WW)
                    ? gy*WW + gx : -1;
        idx = tid + 256;
        row = idx / 66; col = idx - row*66;
        gy = y0 - 1 + row; gx = col - 1;
        goff1 = ((unsigned)gy < (unsigned)HH && (unsigned)gx < (unsigned)WW)
                    ? gy*WW + gx : -1;
        idx = tid + 512;
        row = idx / 66; col = idx - row*66;
        gy = y0 - 1 + row; gx = col - 1;
        goff2 = (idx < 660 && (unsigned)gy < (unsigned)HH && (unsigned)gx < (unsigned)WW)
                    ? gy*WW + gx : -1;
    }
    const int woff0 = (tid >> 5)*CC + oc0 + (tid & 31);
    const int woff1 = 8*CC + oc0 + tid;      // only threads < 32

    const float* xbase = inp + (size_t)(b*CC)*HW;

    float rv0, rv1, rv2, rw0, rw1;

#define LOADCI(ci_) do {                                                    \
        const float* p_ = xbase + (ci_)*HW;                                 \
        rv0 = (goff0 >= 0) ? __ldg(p_ + goff0) : 0.f;                       \
        rv1 = (goff1 >= 0) ? __ldg(p_ + goff1) : 0.f;                       \
        rv2 = (goff2 >= 0) ? __ldg(p_ + goff2) : 0.f;                       \
        const float* wp_ = g_Wt + (ci_)*(9*CC);                             \
        rw0 = wp_[woff0];                                                   \
        rw1 = (tid < 32) ? wp_[woff1] : 0.f;                                \
    } while (0)

#define STORECI(buf_, ci_) do {                                             \
        float st_ = s_style[ci_];                                           \
        s_in[buf_][tid]       = make_float2(rv0, rv0);                      \
        s_in[buf_][tid + 256] = make_float2(rv1, rv1);                      \
        if (tid < 148) s_in[buf_][tid + 512] = make_float2(rv2, rv2);       \
        s_w[buf_][tid] = rw0 * st_;                                         \
        if (tid < 32) s_w[buf_][256 + tid] = rw1 * st_;                     \
    } while (0)

#define COMPUTECI(buf_) do {                                                \
        _Pragma("unroll")                                                   \
        for (int dy = 0; dy < 3; dy++) {                                    \
            const u64* rp_ = (const u64*)(&s_in[buf_][(r + dy)*66 + x0]);   \
            u64 in2_[10];                                                   \
            _Pragma("unroll")                                               \
            for (int j = 0; j < 10; j++) in2_[j] = rp_[j];                  \
            _Pragma("unroll")                                               \
            for (int dx = 0; dx < 3; dx++) {                                \
                const int k_ = dy*3 + dx;                                   \
                const ulonglong2* wp_ =                                     \
                    (const ulonglong2*)(&s_w[buf_][k_*32 + g*8]);           \
                ulonglong2 wA_ = wp_[0], wB_ = wp_[1];                      \
                _Pragma("unroll")                                           \
                for (int c = 0; c < 8; c++) {                               \
                    acc[0][c] = ffma2(in2_[c + dx], wA_.x, acc[0][c]);      \
                    acc[1][c] = ffma2(in2_[c + dx], wA_.y, acc[1][c]);      \
                    acc[2][c] = ffma2(in2_[c + dx], wB_.x, acc[2][c]);      \
                    acc[3][c] = ffma2(in2_[c + dx], wB_.y, acc[3][c]);      \
                }                                                           \
            }                                                               \
        }                                                                   \
    } while (0)

    u64 acc[4][8];
    #pragma unroll
    for (int p = 0; p < 4; p++)
        #pragma unroll
        for (int c = 0; c < 8; c++) acc[p][c] = 0ull;

    __syncthreads();          // s_style visible
    LOADCI(0);

    for (int ci = 0; ci < CC; ci += 2) {
        STORECI(0, ci);
        __syncthreads();
        LOADCI(ci + 1);       // LDG latency hidden under COMPUTE(0)
        COMPUTECI(0);
        STORECI(1, ci + 1);
        __syncthreads();
        {
            int cn = (ci + 2 < CC) ? ci + 2 : CC - 1;   // tail: harmless reload
            LOADCI(cn);
        }
        COMPUTECI(1);
    }

#undef LOADCI
#undef STORECI
#undef COMPUTECI

    // ---- epilogue: demod, noise, leaky ReLU ----
    const int y = y0 + r;
    const float* np = noise + b*HW + y*WW + x0;
    float ns[8];
    #pragma unroll
    for (int c = 0; c < 8; c++) ns[c] = np[c];

    #pragma unroll
    for (int p = 0; p < 4; p++) {
        #pragma unroll
        for (int lane = 0; lane < 2; lane++) {
            const int oc = oc0 + g*8 + 2*p + lane;
            const float d  = g_demod[b*CC + oc];
            const float nv = nw[oc];
            float* op = outp + ((size_t)(b*CC + oc)*HH + y)*WW + x0;
            float vv[8];
            #pragma unroll
            for (int c = 0; c < 8; c++) {
                float v = lane ? f2hi(acc[p][c]) : f2lo(acc[p][c]);
                v = v * d + nv * ns[c];
                vv[c] = v > 0.f ? v : 0.2f * v;
            }
            *(float4*)op       = make_float4(vv[0], vv[1], vv[2], vv[3]);
            *(float4*)(op + 4) = make_float4(vv[4], vv[5], vv[6], vv[7]);
        }
    }
}

// ---------------------------------------------------------------------------
extern "C" void kernel_launch(void* const* d_in, const int* in_sizes, int n_in,
                              void* d_out, int out_size) {
    const float* x   = (const float*)d_in[0];
    const float* w1  = (const float*)d_in[1];
    const float* w2  = (const float*)d_in[2];
    const float* n1  = (const float*)d_in[3];
    const float* n2  = (const float*)d_in[4];
    const float* s1w = (const float*)d_in[5];
    const float* s1b = (const float*)d_in[6];
    const float* c1w = (const float*)d_in[7];
    const float* nw1 = (const float*)d_in[8];
    const float* s2w = (const float*)d_in[9];
    const float* s2b = (const float*)d_in[10];
    const float* c2w = (const float*)d_in[11];
    const float* nw2 = (const float*)d_in[12];
    float* out = (float*)d_out;

    dim3 cgrid(HH/8, CC/32, BB);   // 8 x 8 x 16 = 1024 blocks

    // stage 1
    k_style<<<BB, 256>>>(w1, s1w, s1b);
    k_prep <<<CC, 256>>>(c1w);
    k_demod<<<BB, 256>>>();
    k_conv <<<cgrid, 256>>>(x, nullptr, n1, nw1);

    // stage 2 (reuses style/demod/Wt scratch; stream order guarantees safety)
    k_style<<<BB, 256>>>(w2, s2w, s2b);
    k_prep <<<CC, 256>>>(c2w);
    k_demod<<<BB, 256>>>();
    k_conv <<<cgrid, 256>>>(nullptr, out, n2, nw2);
}

// round 5
// speedup vs baseline: 2.8014x; 2.8014x over previous
#include <cuda_runtime.h>
#include <cstdint>

#define BB 16
#define CC 256
#define HH 64
#define WW 64
#define SSD 512
#define HW 4096

// A chunk image: [128 oc][stride 36] floats (cols 0..31 = ci, 32..35 = zero pad)
#define A_STRIDE 36
#define A_CHUNK_FLOATS (128*A_STRIDE)      // 4608
#define A_CHUNK_BYTES  (A_CHUNK_FLOATS*4)  // 18432
#define B_STRIDE 72                        // conflict-free consumer banks

// smem float-index map
#define SM_STY 32                          // styles [256]
#define SM_A0  320                         // 3 x 4608
#define SM_B0  (320 + 3*A_CHUNK_FLOATS)    // 14144, 2 x 2304
#define SM_FLOATS (SM_B0 + 2*32*B_STRIDE)  // 18752
#define SM_BYTES  (SM_FLOATS*4)            // 75008

__device__ float g_inter[BB*CC*HW];
__device__ float g_style[BB*CC];
__device__ float g_demod[BB*CC];
__device__ float g_Rt[CC*CC];
__device__ float g_Wf[9*2*8*A_CHUNK_FLOATS];   // [k][ochalf][cc][A chunk image]

// ---------------- helpers ----------------
__device__ __forceinline__ uint32_t smem_u32(const void* p) {
    uint32_t a;
    asm("{ .reg .u64 t; cvta.to.shared.u64 t, %1; cvt.u32.u64 %0, t; }" : "=r"(a) : "l"(p));
    return a;
}
__device__ __forceinline__ float tf32r(float v) {
    uint32_t r; asm("cvt.rna.tf32.f32 %0, %1;" : "=r"(r) : "f"(v));
    return __uint_as_float(r);
}
__device__ __forceinline__ void mbar_wait(uint32_t mbar, uint32_t parity) {
    asm volatile(
        "{\n\t.reg .pred P;\n\t"
        "WL_%=:\n\t"
        "mbarrier.try_wait.parity.acquire.cta.shared::cta.b64 P, [%0], %1, 0x989680;\n\t"
        "@P bra.uni WD_%=;\n\t"
        "bra.uni WL_%=;\n\t"
        "WD_%=:\n\t}"
        :: "r"(mbar), "r"(parity) : "memory");
}
#define MBAR_INIT(a,n) asm volatile("mbarrier.init.shared.b64 [%0], %1;" :: "r"(a), "r"((uint32_t)(n)) : "memory")

#define MMA_TF32(d, a, b) \
    asm volatile("mma.sync.aligned.m16n8k8.row.col.f32.tf32.tf32.f32 " \
        "{%0,%1,%2,%3}, {%4,%5,%6,%7}, {%8,%9}, {%0,%1,%2,%3};" \
        : "+f"((d)[0]), "+f"((d)[1]), "+f"((d)[2]), "+f"((d)[3]) \
        : "r"((a)[0]), "r"((a)[1]), "r"((a)[2]), "r"((a)[3]), "r"((b)[0]), "r"((b)[1]))

// ---------------- prep kernels ----------------
__global__ void k_style(const float* __restrict__ wv, const float* __restrict__ sw,
                        const float* __restrict__ sb) {
    __shared__ float s[SSD];
    const int b = blockIdx.x, t = threadIdx.x;
    s[t] = wv[b*SSD + t]; s[t+256] = wv[b*SSD + 256 + t];
    __syncthreads();
    float acc = 0.f;
    const float* rw = sw + t*SSD;
    #pragma unroll 8
    for (int j = 0; j < SSD; j++) acc += s[j] * rw[j];
    g_style[b*CC + t] = acc * 0.03125f + sb[t];
}

// Rt + fragment-image weights (tf32 pre-rounded)
__global__ void k_prep(const float* __restrict__ w) {
    const int oc = blockIdx.x, ci = threadIdx.x;
    const float* src = w + (oc*CC + ci)*9;
    float v[9], s2 = 0.f;
    #pragma unroll
    for (int k = 0; k < 9; k++) { v[k] = src[k]; s2 += v[k]*v[k]; }
    g_Rt[ci*CC + oc] = s2;
    const int oh = oc >> 7, ol = oc & 127, cc = ci >> 5, jl = ci & 31;
    #pragma unroll
    for (int k = 0; k < 9; k++)
        g_Wf[(size_t)((k*2 + oh)*8 + cc)*A_CHUNK_FLOATS + ol*A_STRIDE + jl] = tf32r(v[k]);
    if (ci < 4) {  // zero the pad columns
        #pragma unroll
        for (int k = 0; k < 9; k++)
            for (int c2 = 0; c2 < 8; c2++)
                g_Wf[(size_t)((k*2 + oh)*8 + c2)*A_CHUNK_FLOATS + ol*A_STRIDE + 32 + ci] = 0.f;
    }
}

__global__ void k_demod() {
    __shared__ float st2[CC];
    const int b = blockIdx.x, t = threadIdx.x;
    float s = g_style[b*CC + t];
    st2[t] = s*s;
    __syncthreads();
    float acc = 0.f;
    #pragma unroll 8
    for (int i = 0; i < CC; i++) acc += st2[i] * g_Rt[i*CC + t];
    g_demod[b*CC + t] = rsqrtf(acc + 1e-8f);
}

// ---------------- mma.sync tf32 implicit-GEMM conv ----------------
// CTA: 128 oc x 64 px (one image row), 256 threads = 8 warps (4 Mwarps x 2 Nwarps)
// K = 2304 in 72 chunks of 32 ci; A via cp.async.bulk (3-deep), B via STS (2 bufs,
// refilled every 3 chunks; dx handled as consumer column offset).
__global__ __launch_bounds__(256, 2)
void k_conv(const float* __restrict__ xg, float* __restrict__ outg,
            const float* __restrict__ noise, const float* __restrict__ nw,
            int stage1) {
    extern __shared__ float sm[];
    const uint32_t base = smem_u32(sm);

    const float* xin  = stage1 ? xg : g_inter;
    float*       outp = stage1 ? g_inter : outg;

    const int tid = threadIdx.x, wid = tid >> 5, lane = tid & 31;
    const int woc = wid & 3, wnx = wid >> 1 & 1 ? 1 : (wid >> 2); // wnx = wid>>2
    const int wn  = wid >> 2;
    const int y   = blockIdx.x;
    const int ocsel = blockIdx.y;
    const int oc0 = ocsel * 128;
    const int b   = blockIdx.z;
    (void)woc; (void)wnx;

    sm[SM_STY + tid] = g_style[b*CC + tid];
    if (tid == 0) { MBAR_INIT(base+0, 1); MBAR_INIT(base+8, 1); MBAR_INIT(base+16, 1); }
    __syncthreads();

#define BULKA(c_) do { \
        int cc_ = (c_)/9, k_ = (c_) - cc_*9; \
        const float* src_ = g_Wf + (size_t)((k_*2 + ocsel)*8 + cc_)*A_CHUNK_FLOATS; \
        uint32_t dst_ = base + (uint32_t)(SM_A0 + ((c_)%3)*A_CHUNK_FLOATS)*4u; \
        uint32_t mb_  = base + (uint32_t)(((c_)%3)*8); \
        asm volatile("mbarrier.arrive.expect_tx.shared.b64 _, [%0], %1;" \
            :: "r"(mb_), "r"((uint32_t)A_CHUNK_BYTES) : "memory"); \
        asm volatile("cp.async.bulk.shared::cluster.global.mbarrier::complete_tx::bytes " \
            "[%0], [%1], %2, [%3];" \
            :: "r"(dst_), "l"(src_), "r"((uint32_t)A_CHUNK_BYTES), "r"(mb_) : "memory"); \
    } while (0)

    // B fill staging
    const int bj = tid >> 3;        // ci-local row 0..31
    const int bq = tid & 7;         // col octet
    float4 bv0, bv1;

#define LOADB(c_) do { \
        int cc_ = (c_)/9, k_ = (c_) - cc_*9, dy_ = k_/3; \
        int gy_ = y + dy_ - 1; \
        bool ok_ = (unsigned)gy_ < (unsigned)HH; \
        const float4* p_ = (const float4*)(xin + (size_t)((b*CC + cc_*32 + bj))*HW + gy_*WW + bq*8); \
        bv0 = ok_ ? p_[0] : make_float4(0.f,0.f,0.f,0.f); \
        bv1 = ok_ ? p_[1] : make_float4(0.f,0.f,0.f,0.f); \
    } while (0)

#define STOREB(pb_, c_) do { \
        int cc_ = (c_)/9; \
        float st_ = sm[SM_STY + cc_*32 + bj]; \
        float* d_ = sm + SM_B0 + (pb_)*(32*B_STRIDE) + bj*B_STRIDE; \
        ((float4*)(d_ + 4 + bq*8))[0] = make_float4(tf32r(bv0.x*st_), tf32r(bv0.y*st_), \
                                                    tf32r(bv0.z*st_), tf32r(bv0.w*st_)); \
        ((float4*)(d_ + 8 + bq*8))[0] = make_float4(tf32r(bv1.x*st_), tf32r(bv1.y*st_), \
                                                    tf32r(bv1.z*st_), tf32r(bv1.w*st_)); \
        if (bq == 0) { \
            ((float4*)(d_))[0]      = make_float4(0.f,0.f,0.f,0.f); \
            ((float4*)(d_ + 68))[0] = make_float4(0.f,0.f,0.f,0.f); \
        } \
    } while (0)

    float acc[2][4][4];
    #pragma unroll
    for (int m = 0; m < 2; m++)
        #pragma unroll
        for (int n = 0; n < 4; n++)
            #pragma unroll
            for (int i = 0; i < 4; i++) acc[m][n][i] = 0.f;

    const uint32_t aoff = (uint32_t)((woc*32 + (lane >> 2))*A_STRIDE + (lane & 3));
    const uint32_t boff = (uint32_t)((lane & 3)*B_STRIDE + wn*32 + (lane >> 2));

#define COMPUTE(c_) do { \
        const float* sA_ = sm + SM_A0 + ((c_)%3)*A_CHUNK_FLOATS; \
        int dx_ = ((c_)%9)%3; \
        const float* sB_ = sm + SM_B0 + ((((c_)/3)&1))*(32*B_STRIDE) + dx_ + 3; \
        _Pragma("unroll") \
        for (int ks = 0; ks < 4; ks++) { \
            uint32_t af_[2][4]; \
            _Pragma("unroll") \
            for (int m = 0; m < 2; m++) { \
                const float* ap_ = sA_ + aoff + m*(16*A_STRIDE) + ks*8; \
                af_[m][0] = __float_as_uint(ap_[0]); \
                af_[m][1] = __float_as_uint(ap_[8*A_STRIDE]); \
                af_[m][2] = __float_as_uint(ap_[4]); \
                af_[m][3] = __float_as_uint(ap_[8*A_STRIDE + 4]); \
            } \
            uint32_t bf_[4][2]; \
            _Pragma("unroll") \
            for (int n = 0; n < 4; n++) { \
                const float* bp_ = sB_ + boff + ks*(8*B_STRIDE) + n*8; \
                bf_[n][0] = __float_as_uint(bp_[0]); \
                bf_[n][1] = __float_as_uint(bp_[4*B_STRIDE]); \
            } \
            _Pragma("unroll") \
            for (int n = 0; n < 4; n++) \
                _Pragma("unroll") \
                for (int m = 0; m < 2; m++) \
                    MMA_TF32(acc[m][n], af_[m], bf_[n]); \
        } \
    } while (0)

    // ---- pipeline ----
    LOADB(0);
    if (tid == 0) { BULKA(0); BULKA(1); }
    int ph0 = 0, ph1 = 0, ph2 = 0;

    for (int c = 0; c < 72; c++) {
        if (c % 3 == 0) STOREB((c/3) & 1, c);
        __syncthreads();
        if (tid == 0 && c + 2 < 72) BULKA(c + 2);
        if ((c + 1) % 3 == 0 && c + 1 < 72) LOADB(c + 1);
        const int mb = c % 3;
        if      (mb == 0) { mbar_wait(base + 0,  ph0); ph0 ^= 1; }
        else if (mb == 1) { mbar_wait(base + 8,  ph1); ph1 ^= 1; }
        else              { mbar_wait(base + 16, ph2); ph2 ^= 1; }
        COMPUTE(c);
    }

#undef BULKA
#undef LOADB
#undef STOREB
#undef COMPUTE

    // ---- epilogue: demod, noise, leaky ReLU ----
    const int r   = lane >> 2, tig = lane & 3;
    #pragma unroll
    for (int m = 0; m < 2; m++) {
        const int ocA = oc0 + woc*32 + m*16 + r;
        const int ocB = ocA + 8;
        const float dA = __ldg(&g_demod[b*CC + ocA]);
        const float dB = __ldg(&g_demod[b*CC + ocB]);
        const float nA = __ldg(&nw[ocA]);
        const float nB = __ldg(&nw[ocB]);
        #pragma unroll
        for (int n = 0; n < 4; n++) {
            const int col = wn*32 + n*8 + tig*2;
            const float2 nz = *(const float2*)(noise + (size_t)b*HW + y*WW + col);
            float v0 = acc[m][n][0]*dA + nA*nz.x;
            float v1 = acc[m][n][1]*dA + nA*nz.y;
            float v2 = acc[m][n][2]*dB + nB*nz.x;
            float v3 = acc[m][n][3]*dB + nB*nz.y;
            v0 = v0 > 0.f ? v0 : 0.2f*v0;
            v1 = v1 > 0.f ? v1 : 0.2f*v1;
            v2 = v2 > 0.f ? v2 : 0.2f*v2;
            v3 = v3 > 0.f ? v3 : 0.2f*v3;
            *(float2*)(outp + (size_t)(b*CC + ocA)*HW + y*WW + col) = make_float2(v0, v1);
            *(float2*)(outp + (size_t)(b*CC + ocB)*HW + y*WW + col) = make_float2(v2, v3);
        }
    }
}

// ---------------------------------------------------------------------------
extern "C" void kernel_launch(void* const* d_in, const int* in_sizes, int n_in,
                              void* d_out, int out_size) {
    const float* x   = (const float*)d_in[0];
    const float* w1  = (const float*)d_in[1];
    const float* w2  = (const float*)d_in[2];
    const float* n1  = (const float*)d_in[3];
    const float* n2  = (const float*)d_in[4];
    const float* s1w = (const float*)d_in[5];
    const float* s1b = (const float*)d_in[6];
    const float* c1w = (const float*)d_in[7];
    const float* nw1 = (const float*)d_in[8];
    const float* s2w = (const float*)d_in[9];
    const float* s2b = (const float*)d_in[10];
    const float* c2w = (const float*)d_in[11];
    const float* nw2 = (const float*)d_in[12];
    float* out = (float*)d_out;

    static int configured = 0;
    if (!configured) {
        cudaFuncSetAttribute(k_conv, cudaFuncAttributeMaxDynamicSharedMemorySize, SM_BYTES);
        configured = 1;
    }

    dim3 cgrid(HH, 2, BB);   // 64 rows x 2 oc halves x 16 batches

    k_style<<<BB, 256>>>(w1, s1w, s1b);
    k_prep <<<CC, 256>>>(c1w);
    k_demod<<<BB, 256>>>();
    k_conv <<<cgrid, 256, SM_BYTES>>>(x, out, n1, nw1, 1);

    k_style<<<BB, 256>>>(w2, s2w, s2b);
    k_prep <<<CC, 256>>>(c2w);
    k_demod<<<BB, 256>>>();
    k_conv <<<cgrid, 256, SM_BYTES>>>(x, out, n2, nw2, 0);
}